// round 15
// baseline (speedup 1.0000x reference)
#include <cuda_runtime.h>
#include <cstdint>

#define B_ 32
#define S_ 2048
#define D_ 64
// (1/sqrt(512)) * log2(e): exp(logit) == exp2(mma_result)
#define SCALE2_ (0.044194173824159216f * 1.4426950408889634f)

#define QHST 40  // f16-pair words per Q/K row; (4g+e mod 16 distinct) -> LDS.64 ok
#define KHST 40
#define VPST 72  // pair-packed V rows: 64 data words + 8 pad; banks 8e+g distinct
#define KFST 68  // f32 staging strides
#define VFST 68

// smem byte offsets
#define OFF_QH  0        // 128*40*4 = 20480
#define OFF_KH0 20480    // 64*40*4 = 10240
#define OFF_KH1 30720
#define OFF_VP0 40960    // 32*72*4 = 9216
#define OFF_VP1 50176
#define OFF_KF  59392    // 64*68*4 = 17408 (single f32 staging)
#define OFF_VF  76800    // 64*68*4 = 17408
#define SMEM_TOTAL 94208 // 92 KB -> 2 CTAs/SM

__device__ __forceinline__ uint32_t pk2(float lo, float hi) {
    uint32_t r;
    asm("cvt.rn.f16x2.f32 %0, %1, %2;" : "=r"(r) : "f"(hi), "f"(lo));
    return r;
}
__device__ __forceinline__ float ex2f(float x) {
    float r;
    asm("ex2.approx.f32 %0, %1;" : "=f"(r) : "f"(x));
    return r;
}
// branchless mask factor: m==0 -> 1.0f, m==1 -> 0.0f  (IADD+AND, no predicates)
__device__ __forceinline__ float mfac(int m) {
    return __int_as_float((m - 1) & 0x3F800000);
}
__device__ __forceinline__ void mma16(float (&d)[4], uint32_t a0, uint32_t a1,
                                      uint32_t a2, uint32_t a3,
                                      uint32_t b0, uint32_t b1) {
    asm volatile(
        "mma.sync.aligned.m16n8k16.row.col.f32.f16.f16.f32 "
        "{%0,%1,%2,%3}, {%4,%5,%6,%7}, {%8,%9}, {%0,%1,%2,%3};"
        : "+f"(d[0]), "+f"(d[1]), "+f"(d[2]), "+f"(d[3])
        : "r"(a0), "r"(a1), "r"(a2), "r"(a3), "r"(b0), "r"(b1));
}
__device__ __forceinline__ void cp16(uint32_t dst, const void* src) {
    asm volatile("cp.async.cg.shared.global [%0], [%1], 16;"
                 :: "r"(dst), "l"(src) : "memory");
}
#define CP_COMMIT() asm volatile("cp.async.commit_group;" ::: "memory")
#define CP_WAIT(n)  asm volatile("cp.async.wait_group %0;" :: "n"(n) : "memory")

__device__ __forceinline__ uint32_t smem_u32(const void* p) {
    uint32_t a;
    asm("{ .reg .u64 t; cvta.to.shared.u64 t, %1; cvt.u32.u64 %0, t; }"
        : "=r"(a) : "l"(p));
    return a;
}

// =============================================================================
// Fused attention, f16 m16n8k16 MMAs, Q fragments register-resident.
//   CTA = 128 q-rows, 8 warps x 16 rows. grid (16, 32), 256 thr, 2 CTAs/SM.
//   INVARIANT 1: convert units read EXACTLY the staging chunks the same thread
//   cp.async'd (self-visibility after wait_group; no race).
//   INVARIANT 2: Vp rows are 64 data words (pair-packed d=0..63), stride 72.
//   Q/K pair storage pi-permuted [0,4,1,5,2,6,3,7] per 16-half group.
// =============================================================================
__global__ __launch_bounds__(256, 2) void fused_attn_kernel(
        const float* __restrict__ q, const float* __restrict__ k,
        const float* __restrict__ v, const int* __restrict__ mask,
        float* __restrict__ attn, float* __restrict__ out) {
    extern __shared__ char sm[];
    uint32_t* Qh = (uint32_t*)(sm + OFF_QH);
    float*    Kf = (float*)(sm + OFF_KF);
    float*    Vf = (float*)(sm + OFF_VF);
    const uint32_t smb = smem_u32(sm);

    const int tid = threadIdx.x, lane = tid & 31, wid = tid >> 5;
    const int wm = wid * 16;          // warp's 16 q-rows
    const int g = lane >> 2, e = lane & 3;
    const int b = blockIdx.y, i0 = blockIdx.x * 128;

    const float* kg = k + (size_t)b * S_ * D_;
    const float* vg = v + (size_t)b * S_ * D_;

    // copy-unit coordinates (match convert units!)
    const int krow = tid & 63, kcg = tid >> 6;     // K: 1 row, 16 cols
    const int vjp  = tid & 31, vbb = tid >> 5;     // V: rows 2jp,2jp+1, 8 cols

    // ---- prologue: cp.async K0,V0 (f32) into staging, matched units ----
    {
        const float* ks = kg + krow * D_ + kcg * 16;
        uint32_t kd = smb + OFF_KF + krow * (KFST * 4) + kcg * 64;
        cp16(kd, ks); cp16(kd + 16, ks + 4);
        cp16(kd + 32, ks + 8); cp16(kd + 48, ks + 12);
        const float* vs = vg + (2 * vjp) * D_ + vbb * 8;
        uint32_t vd = smb + OFF_VF + (2 * vjp) * (VFST * 4) + vbb * 32;
        cp16(vd, vs); cp16(vd + 16, vs + 4);
        cp16(vd + VFST * 4, vs + D_); cp16(vd + VFST * 4 + 16, vs + D_ + 4);
        CP_COMMIT();
    }

    // ---- stage Q once: f32 gmem -> f16 pairs, pi-permuted, scale folded ----
    const float* qg = q + ((size_t)b * S_ + i0) * D_;
    #pragma unroll
    for (int u = 0; u < 2; u++) {
        int idx = tid + u * 256;          // 512 units
        int row = idx >> 2, cg = idx & 3; // 16-half group cg of row
        const float* src = qg + row * D_ + cg * 16;
        uint32_t r[8];
        #pragma unroll
        for (int i = 0; i < 4; i++) {
            float4 t = *(const float4*)(src + 4 * i);
            r[2 * i]     = pk2(t.x * SCALE2_, t.y * SCALE2_);
            r[2 * i + 1] = pk2(t.z * SCALE2_, t.w * SCALE2_);
        }
        uint32_t* dst = Qh + row * QHST + cg * 8;
        // pi order: words 0..7 hold pairs [0,4,1,5,2,6,3,7]
        uint4 w0 = { r[0], r[4], r[1], r[5] };
        uint4 w1 = { r[2], r[6], r[3], r[7] };
        *(uint4*)dst = w0;
        *(uint4*)(dst + 4) = w1;
    }
    __syncthreads();  // publish Q

    // ---- hoist Q fragments into registers (loop-invariant) ----
    uint2 qfa[4], qfb[4];
    #pragma unroll
    for (int ks = 0; ks < 4; ++ks) {
        qfa[ks] = *(const uint2*)(Qh + (wm + g) * QHST + ks * 8 + 2 * e);
        qfb[ks] = *(const uint2*)(Qh + (wm + 8 + g) * QHST + ks * 8 + 2 * e);
    }

    const size_t rowg  = ((size_t)b * S_ + i0 + wm + g) * S_;
    const size_t rowg8 = rowg + 8 * (size_t)S_;

    float accpv[8][4];
    #pragma unroll
    for (int dj = 0; dj < 8; dj++)
        #pragma unroll
        for (int c = 0; c < 4; c++) accpv[dj][c] = 0.f;
    float rsum0 = 0.f, rsum1 = 0.f;

    #pragma unroll 1
    for (int ct = 0; ct < 32; ++ct) {
        const int j0 = ct * 64;
        uint32_t* Kh = (uint32_t*)(sm + ((ct & 1) ? OFF_KH1 : OFF_KH0));
        uint32_t* Vp = (uint32_t*)(sm + ((ct & 1) ? OFF_VP1 : OFF_VP0));

        // this thread's staging chunks for tile ct are visible after wait
        CP_WAIT(0);

        // ---- convert pass (reads ONLY own chunks): f32 -> f16 tiles ----
        {   // K: row krow, cols kcg*16..+15 (pi-permuted pairs)
            const float* src = Kf + krow * KFST + kcg * 16;
            uint32_t r[8];
            #pragma unroll
            for (int i = 0; i < 4; i++) {
                float4 t = *(const float4*)(src + 4 * i);
                r[2 * i]     = pk2(t.x, t.y);
                r[2 * i + 1] = pk2(t.z, t.w);
            }
            uint32_t* dst = Kh + krow * KHST + kcg * 8;
            uint4 w0 = { r[0], r[4], r[1], r[5] };
            uint4 w1 = { r[2], r[6], r[3], r[7] };
            *(uint4*)dst = w0;
            *(uint4*)(dst + 4) = w1;
        }
        {   // V: pair-pack rows 2vjp,2vjp+1, cols vbb*8..+7
            const float* s0 = Vf + (2 * vjp) * VFST + vbb * 8;
            const float* s1 = s0 + VFST;
            float4 t0a = *(const float4*)s0;
            float4 t0b = *(const float4*)(s0 + 4);
            float4 t1a = *(const float4*)s1;
            float4 t1b = *(const float4*)(s1 + 4);
            uint32_t* dst = Vp + vjp * VPST + vbb * 8;
            uint4 w0 = { pk2(t0a.x, t1a.x), pk2(t0a.y, t1a.y),
                         pk2(t0a.z, t1a.z), pk2(t0a.w, t1a.w) };
            uint4 w1 = { pk2(t0b.x, t1b.x), pk2(t0b.y, t1b.y),
                         pk2(t0b.z, t1b.z), pk2(t0b.w, t1b.w) };
            *(uint4*)dst = w0;
            *(uint4*)(dst + 4) = w1;
        }

        // single barrier: f16 tiles published; staging consumed by its owners
        __syncthreads();

        // ---- prefetch tile ct+1 (f32) into staging, matched units ----
        if (ct + 1 < 32) {
            const float* kn = kg + (size_t)(j0 + 64) * D_ + krow * D_ + kcg * 16;
            uint32_t kd = smb + OFF_KF + krow * (KFST * 4) + kcg * 64;
            cp16(kd, kn); cp16(kd + 16, kn + 4);
            cp16(kd + 32, kn + 8); cp16(kd + 48, kn + 12);
            const float* vn = vg + (size_t)(j0 + 64) * D_ + (2 * vjp) * D_ + vbb * 8;
            uint32_t vd = smb + OFF_VF + (2 * vjp) * (VFST * 4) + vbb * 32;
            cp16(vd, vn); cp16(vd + 16, vn + 4);
            cp16(vd + VFST * 4, vn + D_); cp16(vd + VFST * 4 + 16, vn + D_ + 4);
            CP_COMMIT();
        }

        // ---- QK^T: 4 k-steps of 16, warp tile 16x64, Q from registers ----
        float accq[8][4];
        #pragma unroll
        for (int nj = 0; nj < 8; nj++)
            #pragma unroll
            for (int c = 0; c < 4; c++) accq[nj][c] = 0.f;

        #pragma unroll
        for (int ks = 0; ks < 4; ++ks) {
            #pragma unroll
            for (int nj = 0; nj < 8; nj++) {
                uint2 kb = *(const uint2*)(Kh + (nj * 8 + g) * KHST + ks * 8 + 2 * e);
                mma16(accq[nj], qfa[ks].x, qfb[ks].x, qfa[ks].y, qfb[ks].y,
                      kb.x, kb.y);
            }
        }

        // ---- epilogue: branchless mask -> exp2 -> attn store + rowsum ----
        float sg = 0.f, sg8 = 0.f;
        #pragma unroll
        for (int nj = 0; nj < 8; nj++) {
            int co = j0 + nj * 8 + 2 * e;
            int2 mg = *(const int2*)(mask + rowg + co);
            int2 mh = *(const int2*)(mask + rowg8 + co);
            float e0 = ex2f(accq[nj][0]) * mfac(mg.x);
            float e1 = ex2f(accq[nj][1]) * mfac(mg.y);
            float e2 = ex2f(accq[nj][2]) * mfac(mh.x);
            float e3 = ex2f(accq[nj][3]) * mfac(mh.y);
            sg += e0 + e1;
            sg8 += e2 + e3;
            float2 w0 = { e0, e1 };
            float2 w1 = { e2, e3 };
            *(float2*)(attn + rowg + co) = w0;
            *(float2*)(attn + rowg8 + co) = w1;
            accq[nj][0] = e0; accq[nj][1] = e1;
            accq[nj][2] = e2; accq[nj][3] = e3;
        }
        sg  += __shfl_xor_sync(0xffffffffu, sg, 1);
        sg  += __shfl_xor_sync(0xffffffffu, sg, 2);
        sg8 += __shfl_xor_sync(0xffffffffu, sg8, 1);
        sg8 += __shfl_xor_sync(0xffffffffu, sg8, 2);
        rsum0 += sg;
        rsum1 += sg8;

        // ---- PV: pack P fragments (f16) straight from C-frags, then MMA ----
        #pragma unroll
        for (int ksj = 0; ksj < 4; ++ksj) {
            uint32_t a0 = pk2(accq[2 * ksj][0], accq[2 * ksj][1]);
            uint32_t a1 = pk2(accq[2 * ksj][2], accq[2 * ksj][3]);
            uint32_t a2 = pk2(accq[2 * ksj + 1][0], accq[2 * ksj + 1][1]);
            uint32_t a3 = pk2(accq[2 * ksj + 1][2], accq[2 * ksj + 1][3]);
            const uint32_t* vr0 = Vp + (8 * ksj + e) * VPST;
            const uint32_t* vr1 = Vp + (8 * ksj + e + 4) * VPST;
            #pragma unroll
            for (int dj = 0; dj < 8; dj++) {
                uint32_t b0 = vr0[dj * 8 + g];
                uint32_t b1 = vr1[dj * 8 + g];
                mma16(accpv[dj], a0, a1, a2, a3, b0, b1);
            }
        }
    }

    // ---- warp-private finish: out = accpv * inv ----
    const float inv0 = __frcp_rn(rsum0);
    const float inv1 = __frcp_rn(rsum1);
    {
        float* o0 = out + ((size_t)b * S_ + i0 + wm + g) * D_;
        float* o1 = out + ((size_t)b * S_ + i0 + wm + 8 + g) * D_;
        #pragma unroll
        for (int dj = 0; dj < 8; dj++) {
            float2 w0 = { accpv[dj][0] * inv0, accpv[dj][1] * inv0 };
            float2 w1 = { accpv[dj][2] * inv1, accpv[dj][3] * inv1 };
            *(float2*)(o0 + dj * 8 + 2 * e) = w0;
            *(float2*)(o1 + dj * 8 + 2 * e) = w1;
        }
    }

    // ---- pass 2 (warp-private rows): normalize attn stripe in place ----
    {
        float* a0 = attn + rowg;
        float* a1 = attn + rowg8;
        #pragma unroll 4
        for (int kk = 0; kk < 128; kk++) {
            int c4 = (e + kk * 4) << 2;
            float4* p0 = (float4*)(a0 + c4);
            float4 t0 = *p0;
            t0.x *= inv0; t0.y *= inv0; t0.z *= inv0; t0.w *= inv0;
            *p0 = t0;
            float4* p1 = (float4*)(a1 + c4);
            float4 t1 = *p1;
            t1.x *= inv1; t1.y *= inv1; t1.z *= inv1; t1.w *= inv1;
            *p1 = t1;
        }
    }
}

// =============================================================================
extern "C" void kernel_launch(void* const* d_in, const int* in_sizes, int n_in,
                              void* d_out, int out_size) {
    const float* q = (const float*)d_in[0];
    const float* k = (const float*)d_in[1];
    const float* v = (const float*)d_in[2];
    const int* mask = (const int*)d_in[3];

    float* out  = (float*)d_out;                 // [B,S,D]
    float* attn = out + (size_t)B_ * S_ * D_;    // [B,S,S]

    cudaFuncSetAttribute(fused_attn_kernel,
                         cudaFuncAttributeMaxDynamicSharedMemorySize, SMEM_TOTAL);

    dim3 grid(S_ / 128, B_);
    fused_attn_kernel<<<grid, 256, SMEM_TOTAL>>>(q, k, v, mask, attn, out);
}

// round 16
// speedup vs baseline: 1.1097x; 1.1097x over previous
#include <cuda_runtime.h>
#include <cstdint>

#define B_ 32
#define S_ 2048
#define D_ 64
// (1/sqrt(512)) * log2(e): exp(logit) == exp2(mma_result)
#define SCALE2_ (0.044194173824159216f * 1.4426950408889634f)

#define KHST 40  // f16-pair words per Q/K row; LDS.64 conflict-free
#define QHST 40
#define VPST 72  // pair-packed V rows: 64 data words + 8 pad

#define NST 3    // ring stages

// smem byte offsets
#define OFF_QH  0                      // 128*40*4 = 20480
#define OFF_KH  20480                  // 3 stages x 64*40*4 = 10240
#define KH_SZ   10240
#define OFF_VP  51200                  // 3 stages x 32*72*4 = 9216
#define VP_SZ   9216
#define OFF_MB  78848                  // 9 mbarriers x 8B
#define SMEM_TOTAL 79104               // ~77.3 KB -> 2 CTAs/SM

__device__ __forceinline__ uint32_t pk2(float lo, float hi) {
    uint32_t r;
    asm("cvt.rn.f16x2.f32 %0, %1, %2;" : "=r"(r) : "f"(hi), "f"(lo));
    return r;
}
__device__ __forceinline__ float pexp2(int m, float x) {
    float r;
    asm("{\n\t.reg .pred p;\n\t"
        "setp.eq.s32 p, %1, 0;\n\t"
        "mov.f32 %0, 0f00000000;\n\t"
        "@p ex2.approx.f32 %0, %2;\n\t}"
        : "=f"(r) : "r"(m), "f"(x));
    return r;
}
__device__ __forceinline__ void mma16(float (&d)[4], uint32_t a0, uint32_t a1,
                                      uint32_t a2, uint32_t a3,
                                      uint32_t b0, uint32_t b1) {
    asm volatile(
        "mma.sync.aligned.m16n8k16.row.col.f32.f16.f16.f32 "
        "{%0,%1,%2,%3}, {%4,%5,%6,%7}, {%8,%9}, {%0,%1,%2,%3};"
        : "+f"(d[0]), "+f"(d[1]), "+f"(d[2]), "+f"(d[3])
        : "r"(a0), "r"(a1), "r"(a2), "r"(a3), "r"(b0), "r"(b1));
}
__device__ __forceinline__ uint32_t smem_u32(const void* p) {
    uint32_t a;
    asm("{ .reg .u64 t; cvta.to.shared.u64 t, %1; cvt.u32.u64 %0, t; }"
        : "=r"(a) : "l"(p));
    return a;
}
// ---- base-PTX mbarrier (sm_80 feature set; NOT arch-accelerated) ----
__device__ __forceinline__ void mb_init(uint32_t a, uint32_t cnt) {
    asm volatile("mbarrier.init.shared.b64 [%0], %1;" :: "r"(a), "r"(cnt) : "memory");
}
__device__ __forceinline__ void mb_arrive(uint32_t a) {
    asm volatile("{ .reg .b64 st; mbarrier.arrive.shared.b64 st, [%0]; }"
                 :: "r"(a) : "memory");
}
__device__ __forceinline__ void mb_wait(uint32_t a, uint32_t ph) {
    uint32_t done;
    do {
        asm volatile(
            "{ .reg .pred p; mbarrier.test_wait.parity.shared.b64 p, [%1], %2; "
            "selp.b32 %0, 1, 0, p; }"
            : "=r"(done) : "r"(a), "r"(ph) : "memory");
        if (!done) __nanosleep(32);
    } while (!done);
}

// =============================================================================
// Fused attention, producer/consumer warp-specialized, mbarrier ring (no
// __syncthreads in the main loop -> no phase-locked convoys).
//   CTA = 320 thr: warps 0-7 consumers (16 q-rows each), warp 8 K-prod,
//   warp 9 V-prod. grid (16, 32), 2 CTAs/SM.
//   Consumer math identical to the 574us R14 kernel (f16 m16n8k16,
//   pi-permuted Kh, pair-packed Vp, C-frag->A-frag PV).
// =============================================================================
__global__ __launch_bounds__(320, 2) void fused_attn_kernel(
        const float* __restrict__ q, const float* __restrict__ k,
        const float* __restrict__ v, const int* __restrict__ mask,
        float* __restrict__ attn, float* __restrict__ out) {
    extern __shared__ char sm[];
    uint32_t* Qh = (uint32_t*)(sm + OFF_QH);
    const uint32_t smb = smem_u32(sm);

    const int tid = threadIdx.x, lane = tid & 31, wid = tid >> 5;
    const int b = blockIdx.y, i0 = blockIdx.x * 128;

    const float* kg = k + (size_t)b * S_ * D_;
    const float* vg = v + (size_t)b * S_ * D_;

    // mbarrier addresses
    const uint32_t mbF_K = smb + OFF_MB;        // fullK[s]  (count 32)
    const uint32_t mbF_V = smb + OFF_MB + 24;   // fullV[s]  (count 32)
    const uint32_t mbE   = smb + OFF_MB + 48;   // empty[s]  (count 256)

    if (tid == 0) {
        #pragma unroll
        for (int s = 0; s < NST; s++) {
            mb_init(mbF_K + s * 8, 32);
            mb_init(mbF_V + s * 8, 32);
            mb_init(mbE + s * 8, 256);
        }
    }

    // ---- stage Q once (consumers' 256 threads): f16 pairs, pi-permuted ----
    if (tid < 256) {
        const float* qg = q + ((size_t)b * S_ + i0) * D_;
        #pragma unroll
        for (int u = 0; u < 2; u++) {
            int idx = tid + u * 256;
            int row = idx >> 2, cg = idx & 3;
            const float* src = qg + row * D_ + cg * 16;
            uint32_t r[8];
            #pragma unroll
            for (int i = 0; i < 4; i++) {
                float4 t = *(const float4*)(src + 4 * i);
                r[2 * i]     = pk2(t.x * SCALE2_, t.y * SCALE2_);
                r[2 * i + 1] = pk2(t.z * SCALE2_, t.w * SCALE2_);
            }
            uint32_t* dst = Qh + row * QHST + cg * 8;
            uint4 w0 = { r[0], r[4], r[1], r[5] };
            uint4 w1 = { r[2], r[6], r[3], r[7] };
            *(uint4*)dst = w0;
            *(uint4*)(dst + 4) = w1;
        }
    }
    __syncthreads();  // publish Q + mbarrier inits; ONLY CTA-wide barrier

    if (wid == 8) {
        // ================== K producer ==================
        int s = 0, pe = 1;  // empty-wait parity (flipped trick: first passes)
        #pragma unroll 1
        for (int ct = 0; ct < 32; ++ct) {
            mb_wait(mbE + s * 8, (uint32_t)pe);
            __threadfence_block();
            uint32_t* Kh = (uint32_t*)(sm + OFF_KH + s * KH_SZ);
            const float* kt = kg + (size_t)(ct * 64) * D_;
            #pragma unroll 4
            for (int t = 0; t < 32; t++) {
                int ff = t * 32 + lane;          // flat float4 index
                int row = ff >> 4, i4 = ff & 15;
                int cg = i4 >> 2, i = i4 & 3;
                float4 tv = __ldg((const float4*)(kt + row * D_ + i4 * 4));
                uint32_t w0 = pk2(tv.x, tv.y);
                uint32_t w1 = pk2(tv.z, tv.w);
                int pos0 = (i < 2) ? (cg * 8 + 4 * i) : (cg * 8 + 4 * (i - 2) + 1);
                Kh[row * KHST + pos0]     = w0;
                Kh[row * KHST + pos0 + 2] = w1;
            }
            __threadfence_block();
            mb_arrive(mbF_K + s * 8);
            if (++s == NST) { s = 0; pe ^= 1; }
        }
    } else if (wid == 9) {
        // ================== V producer ==================
        int s = 0, pe = 1;
        #pragma unroll 1
        for (int ct = 0; ct < 32; ++ct) {
            mb_wait(mbE + s * 8, (uint32_t)pe);
            __threadfence_block();
            uint32_t* Vp = (uint32_t*)(sm + OFF_VP + s * VP_SZ);
            const float* vt = vg + (size_t)(ct * 64) * D_;
            #pragma unroll 4
            for (int t = 0; t < 16; t++) {
                int ff = t * 32 + lane;          // flat pair-row float4 index
                int jp = ff >> 4, q4 = ff & 15;
                const float* s0 = vt + (2 * jp) * D_ + q4 * 4;
                float4 a = __ldg((const float4*)s0);
                float4 c = __ldg((const float4*)(s0 + D_));
                uint4 w = { pk2(a.x, c.x), pk2(a.y, c.y),
                            pk2(a.z, c.z), pk2(a.w, c.w) };
                *(uint4*)(Vp + jp * VPST + q4 * 4) = w;
            }
            __threadfence_block();
            mb_arrive(mbF_V + s * 8);
            if (++s == NST) { s = 0; pe ^= 1; }
        }
    } else {
        // ================== consumers (warps 0-7) ==================
        const int wm = wid * 16;
        const int g = lane >> 2, e = lane & 3;
        const size_t rowg  = ((size_t)b * S_ + i0 + wm + g) * S_;
        const size_t rowg8 = rowg + 8 * (size_t)S_;

        float accpv[8][4];
        #pragma unroll
        for (int dj = 0; dj < 8; dj++)
            #pragma unroll
            for (int c = 0; c < 4; c++) accpv[dj][c] = 0.f;
        float rsum0 = 0.f, rsum1 = 0.f;

        int s = 0, ph = 0;
        #pragma unroll 1
        for (int ct = 0; ct < 32; ++ct) {
            const int j0 = ct * 64;
            uint32_t* Kh = (uint32_t*)(sm + OFF_KH + s * KH_SZ);
            uint32_t* Vp = (uint32_t*)(sm + OFF_VP + s * VP_SZ);

            mb_wait(mbF_K + s * 8, (uint32_t)ph);
            __threadfence_block();

            // ---- QK^T: 4 k-steps of 16, warp tile 16x64 ----
            float accq[8][4];
            #pragma unroll
            for (int nj = 0; nj < 8; nj++)
                #pragma unroll
                for (int c = 0; c < 4; c++) accq[nj][c] = 0.f;

            #pragma unroll
            for (int ks = 0; ks < 4; ++ks) {
                uint2 qa = *(const uint2*)(Qh + (wm + g) * QHST + ks * 8 + 2 * e);
                uint2 qb = *(const uint2*)(Qh + (wm + 8 + g) * QHST + ks * 8 + 2 * e);
                #pragma unroll
                for (int nj = 0; nj < 8; nj++) {
                    uint2 kb = *(const uint2*)(Kh + (nj * 8 + g) * KHST + ks * 8 + 2 * e);
                    mma16(accq[nj], qa.x, qb.x, qa.y, qb.y, kb.x, kb.y);
                }
            }

            // ---- epilogue: mask -> exp2 -> attn store + rowsum ----
            float sg = 0.f, sg8 = 0.f;
            #pragma unroll
            for (int nj = 0; nj < 8; nj++) {
                int co = j0 + nj * 8 + 2 * e;
                int2 mg = *(const int2*)(mask + rowg + co);
                int2 mh = *(const int2*)(mask + rowg8 + co);
                float e0 = pexp2(mg.x, accq[nj][0]);
                float e1 = pexp2(mg.y, accq[nj][1]);
                float e2 = pexp2(mh.x, accq[nj][2]);
                float e3 = pexp2(mh.y, accq[nj][3]);
                sg += e0 + e1;
                sg8 += e2 + e3;
                float2 w0 = { e0, e1 };
                float2 w1 = { e2, e3 };
                *(float2*)(attn + rowg + co) = w0;
                *(float2*)(attn + rowg8 + co) = w1;
                accq[nj][0] = e0; accq[nj][1] = e1;
                accq[nj][2] = e2; accq[nj][3] = e3;
            }
            sg  += __shfl_xor_sync(0xffffffffu, sg, 1);
            sg  += __shfl_xor_sync(0xffffffffu, sg, 2);
            sg8 += __shfl_xor_sync(0xffffffffu, sg8, 1);
            sg8 += __shfl_xor_sync(0xffffffffu, sg8, 2);
            rsum0 += sg;
            rsum1 += sg8;

            mb_wait(mbF_V + s * 8, (uint32_t)ph);
            __threadfence_block();

            // ---- PV: pack P fragments straight from C-frags, then MMA ----
            #pragma unroll
            for (int ksj = 0; ksj < 4; ++ksj) {
                uint32_t a0 = pk2(accq[2 * ksj][0], accq[2 * ksj][1]);
                uint32_t a1 = pk2(accq[2 * ksj][2], accq[2 * ksj][3]);
                uint32_t a2 = pk2(accq[2 * ksj + 1][0], accq[2 * ksj + 1][1]);
                uint32_t a3 = pk2(accq[2 * ksj + 1][2], accq[2 * ksj + 1][3]);
                const uint32_t* vr0 = Vp + (8 * ksj + e) * VPST;
                const uint32_t* vr1 = Vp + (8 * ksj + e + 4) * VPST;
                #pragma unroll
                for (int dj = 0; dj < 8; dj++) {
                    uint32_t b0 = vr0[dj * 8 + g];
                    uint32_t b1 = vr1[dj * 8 + g];
                    mma16(accpv[dj], a0, a1, a2, a3, b0, b1);
                }
            }

            mb_arrive(mbE + s * 8);   // done with stage s (Kh and Vp)
            if (++s == NST) { s = 0; ph ^= 1; }
        }

        // ---- finish: out = accpv * inv ----
        const float inv0 = __frcp_rn(rsum0);
        const float inv1 = __frcp_rn(rsum1);
        {
            float* o0 = out + ((size_t)b * S_ + i0 + wm + g) * D_;
            float* o1 = out + ((size_t)b * S_ + i0 + wm + 8 + g) * D_;
            #pragma unroll
            for (int dj = 0; dj < 8; dj++) {
                float2 w0 = { accpv[dj][0] * inv0, accpv[dj][1] * inv0 };
                float2 w1 = { accpv[dj][2] * inv1, accpv[dj][3] * inv1 };
                *(float2*)(o0 + dj * 8 + 2 * e) = w0;
                *(float2*)(o1 + dj * 8 + 2 * e) = w1;
            }
        }

        // ---- pass 2 (warp-private rows): normalize attn stripe in place ----
        {
            float* a0 = attn + rowg;
            float* a1 = attn + rowg8;
            #pragma unroll 4
            for (int kk = 0; kk < 128; kk++) {
                int c4 = (e + kk * 4) << 2;
                float4* p0 = (float4*)(a0 + c4);
                float4 t0 = *p0;
                t0.x *= inv0; t0.y *= inv0; t0.z *= inv0; t0.w *= inv0;
                *p0 = t0;
                float4* p1 = (float4*)(a1 + c4);
                float4 t1 = *p1;
                t1.x *= inv1; t1.y *= inv1; t1.z *= inv1; t1.w *= inv1;
                *p1 = t1;
            }
        }
    }
}

// =============================================================================
extern "C" void kernel_launch(void* const* d_in, const int* in_sizes, int n_in,
                              void* d_out, int out_size) {
    const float* q = (const float*)d_in[0];
    const float* k = (const float*)d_in[1];
    const float* v = (const float*)d_in[2];
    const int* mask = (const int*)d_in[3];

    float* out  = (float*)d_out;                 // [B,S,D]
    float* attn = out + (size_t)B_ * S_ * D_;    // [B,S,S]

    cudaFuncSetAttribute(fused_attn_kernel,
                         cudaFuncAttributeMaxDynamicSharedMemorySize, SMEM_TOTAL);

    dim3 grid(S_ / 128, B_);
    fused_attn_kernel<<<grid, 320, SMEM_TOTAL>>>(q, k, v, mask, attn, out);
}